// round 15
// baseline (speedup 1.0000x reference)
#include <cuda_runtime.h>
#include <cstdint>

// Problem constants
#define BB 8
#define TT 1024
#define CC 768
#define HH 12
#define DD 64
#define NTOK (BB * TT)      // 8192
#define NQKV (3 * CC)       // 2304

// Scratch (device globals; no runtime allocation allowed)
__device__ float g_q[BB * HH * TT * DD];   // [B,H,T,D], q pre-scaled by log2e/8
__device__ float g_k[BB * HH * TT * DD];   // [B,H,T,D]
__device__ float g_v[BB * HH * TT * DD];   // [B,H,D,T]  (TRANSPOSED for ldmatrix)
__device__ float g_y[BB * TT * CC];        // attention output (tf32-rounded)
__device__ float g_xc[NTOK * CC];          // x, tf32-rounded
__device__ float g_wqc[NQKV * CC];         // w_qkv, TRANSPOSED [n][k], tf32-rounded
__device__ float g_wpc[CC * CC];           // w_proj, TRANSPOSED [n][k], tf32-rounded

// ---------------------------------------------------------------------------
// Helpers (compute_80-level PTX only; no sm_103a-only features)
// ---------------------------------------------------------------------------
__device__ __forceinline__ uint32_t smem_u32(const void* p) {
    uint32_t a;
    asm("{ .reg .u64 t; cvta.to.shared.u64 t, %1; cvt.u32.u64 %0, t; }"
        : "=r"(a) : "l"(p));
    return a;
}
__device__ __forceinline__ uint32_t tf32_bits(float x) {
    uint32_t r;
    asm("cvt.rna.tf32.f32 %0, %1;" : "=r"(r) : "f"(x));
    return r;
}
__device__ __forceinline__ float tf32_round(float x) {
    return __uint_as_float(tf32_bits(x));
}
__device__ __forceinline__ float ex2(float x) {
    float y;
    asm("ex2.approx.ftz.f32 %0, %1;" : "=f"(y) : "f"(x));
    return y;
}
__device__ __forceinline__ void cp_async16(uint32_t dst, const void* src) {
    asm volatile("cp.async.ca.shared.global [%0], [%1], 16;"
                 :: "r"(dst), "l"(src));
}
#define CP_COMMIT() asm volatile("cp.async.commit_group;" ::: "memory")
#define CP_WAIT(n)  asm volatile("cp.async.wait_group %0;" :: "n"(n) : "memory")

// m16n8k8 tf32 mma: D += A*B, fp32 accumulate.
__device__ __forceinline__ void mma_tf32(float* d, const uint32_t* a,
                                         const uint32_t* b) {
    asm volatile(
        "mma.sync.aligned.m16n8k8.row.col.f32.tf32.tf32.f32 "
        "{%0,%1,%2,%3}, {%4,%5,%6,%7}, {%8,%9}, {%0,%1,%2,%3};"
        : "+f"(d[0]), "+f"(d[1]), "+f"(d[2]), "+f"(d[3])
        : "r"(a[0]), "r"(a[1]), "r"(a[2]), "r"(a[3]),
          "r"(b[0]), "r"(b[1]));
}

// ldmatrix x4: four 8x8 b16 matrices == four 8x4 b32 (tf32) submatrices.
#define LDM_X4(r0, r1, r2, r3, addr) \
    asm volatile("ldmatrix.sync.aligned.m8n8.x4.shared.b16 {%0,%1,%2,%3}, [%4];" \
                 : "=r"(r0), "=r"(r1), "=r"(r2), "=r"(r3) : "r"(addr))

// ---------------------------------------------------------------------------
// tf32 rounding of x (no transpose)
// ---------------------------------------------------------------------------
#define N4_X  (NTOK * CC / 4)     // 1572864

__global__ __launch_bounds__(256) void cvt_x_kernel(const float* __restrict__ x)
{
    int i = blockIdx.x * 256 + threadIdx.x;
    if (i >= N4_X) return;
    float4 v = ((const float4*)x)[i];
    uint4 r;
    r.x = tf32_bits(v.x);
    r.y = tf32_bits(v.y);
    r.z = tf32_bits(v.z);
    r.w = tf32_bits(v.w);
    ((uint4*)g_xc)[i] = r;
}

// ---------------------------------------------------------------------------
// Weight transpose + tf32 round: in [K][N] row-major -> out [N][K] row-major.
// Output selected INSIDE device code (which: 0 -> g_wqc, 1 -> g_wpc) —
// device-global addresses must never be passed from host code.
// ---------------------------------------------------------------------------
__global__ __launch_bounds__(256) void cvt_wT_kernel(
    const float* __restrict__ in, int K, int N, int which)
{
    float* outp = which ? g_wpc : g_wqc;
    __shared__ float tile[32][33];
    const int n0 = blockIdx.x * 32;
    const int k0 = blockIdx.y * 32;
    const int tx = threadIdx.x & 31;
    const int ty = threadIdx.x >> 5;   // 0..7
#pragma unroll
    for (int i = 0; i < 32; i += 8)
        tile[ty + i][tx] = in[(size_t)(k0 + ty + i) * N + n0 + tx];
    __syncthreads();
#pragma unroll
    for (int i = 0; i < 32; i += 8)
        outp[(size_t)(n0 + ty + i) * K + k0 + tx] = tf32_round(tile[tx][ty + i]);
}

// ---------------------------------------------------------------------------
// tf32 mma.sync GEMM: out[M,Ntot] = A[M,768] @ W^T + bias, W stored [Ntot][768].
// CTA 128x128, 256 thr (8 warps as 2m x 4n), warp tile 64x32, 3-stage pipeline.
// As AND Bs: row-major-by-{m,n} [128][36]; all fragments via ldmatrix.x4
// (stride 36 -> word bank = 4*row + col: perfect 32-bank coverage).
// ---------------------------------------------------------------------------
#define KTILE 32
#define NIT (CC / KTILE)        // 24
#define ASTRIDE 36
#define ABYTES (128 * ASTRIDE * 4)   // 18432
#define BUFBYTES (2 * ABYTES)        // 36864 (A tile + B tile)
#define NSTAGE 3
#define SMEMB (NSTAGE * BUFBYTES)    // 110592

__device__ __forceinline__ void mm_issue_tile(
    const float* __restrict__ A, const float* __restrict__ W,
    uint32_t sbuf, int m0, int n0, int k0, int tid)
{
#pragma unroll
    for (int i = 0; i < 4; i++) {
        int idx = tid + 256 * i;
        int m = idx >> 3, kq = idx & 7;
        cp_async16(sbuf + (m * ASTRIDE + kq * 4) * 4,
                   A + (size_t)(m0 + m) * CC + k0 + kq * 4);
    }
#pragma unroll
    for (int i = 0; i < 4; i++) {
        int idx = tid + 256 * i;
        int n = idx >> 3, kq = idx & 7;
        cp_async16(sbuf + ABYTES + (n * ASTRIDE + kq * 4) * 4,
                   W + (size_t)(n0 + n) * CC + k0 + kq * 4);
    }
    CP_COMMIT();
}

__global__ void __launch_bounds__(256, 2) mm_mma_kernel(
    const float* __restrict__ bias, float* __restrict__ out,
    int Ntot, int mode)
{
    extern __shared__ __align__(16) char smem[];
    const float* A = (mode == 0) ? g_xc : g_y;
    const float* W = (mode == 0) ? g_wqc : g_wpc;

    const int tid = threadIdx.x;
    const int wid = tid >> 5;
    const int lane = tid & 31;
    const int g = lane >> 2;
    const int c4 = lane & 3;
    const int m0 = blockIdx.y * 128;
    const int n0 = blockIdx.x * 128;
    const int wm = (wid >> 2) * 64;
    const int wn = (wid & 3) * 32;
    const uint32_t sbase = smem_u32(smem);

    // ldmatrix lane geometry
    const int arow_l = ((lane >> 3) & 1) * 8 + (lane & 7);  // A: 0..15
    const int acol_l = (lane >> 4) * 4;                     // A: 0 or 4
    const int bmat = lane >> 3;                             // B: matrix 0..3
    const int brow = lane & 7;
    const int bro = (wn + (bmat >> 1) * 8 + brow) * ASTRIDE + (bmat & 1) * 4;

    float acc[4][4][4];
#pragma unroll
    for (int mt = 0; mt < 4; mt++)
#pragma unroll
        for (int nt = 0; nt < 4; nt++)
#pragma unroll
            for (int i = 0; i < 4; i++) acc[mt][nt][i] = 0.0f;

    mm_issue_tile(A, W, sbase, m0, n0, 0, tid);
    mm_issue_tile(A, W, sbase + BUFBYTES, m0, n0, KTILE, tid);

    int buf = 0, fill = 2;

    for (int t = 0; t < NIT; t++) {
        if (t + 2 < NIT) {
            mm_issue_tile(A, W, sbase + fill * BUFBYTES,
                          m0, n0, (t + 2) * KTILE, tid);
            fill = (fill == 2) ? 0 : fill + 1;
            CP_WAIT(2);
        } else if (t + 1 < NIT) {
            CP_WAIT(1);
        } else {
            CP_WAIT(0);
        }
        __syncthreads();

        const uint32_t sbuf = sbase + buf * BUFBYTES;
        const uint32_t aaddr = sbuf + ((wm + arow_l) * ASTRIDE + acol_l) * 4;
        const uint32_t baddr = sbuf + ABYTES + bro * 4;

#pragma unroll
        for (int kk = 0; kk < KTILE; kk += 8) {
            uint32_t a[4][4], b[4][2];
#pragma unroll
            for (int mt = 0; mt < 4; mt++)
                LDM_X4(a[mt][0], a[mt][1], a[mt][2], a[mt][3],
                       aaddr + (mt * 16 * ASTRIDE + kk) * 4);
            LDM_X4(b[0][0], b[0][1], b[1][0], b[1][1], baddr + kk * 4);
            LDM_X4(b[2][0], b[2][1], b[3][0], b[3][1],
                   baddr + (16 * ASTRIDE + kk) * 4);
#pragma unroll
            for (int mt = 0; mt < 4; mt++)
#pragma unroll
                for (int nt = 0; nt < 4; nt++)
                    mma_tf32(acc[mt][nt], a[mt], b[nt]);
        }
        __syncthreads();
        buf = (buf == 2) ? 0 : buf + 1;
    }

    // Epilogue.  Fragment (mt,nt): rows g,g+8; cols 2c4,2c4+1.
    if (mode == 1) {
#pragma unroll
        for (int mt = 0; mt < 4; mt++) {
#pragma unroll
            for (int nt = 0; nt < 4; nt++) {
                int mg = m0 + wm + mt * 16 + g;
                int ng = n0 + wn + nt * 8 + 2 * c4;
                float b0 = bias[ng], b1 = bias[ng + 1];
                float2 v0 = make_float2(acc[mt][nt][0] + b0, acc[mt][nt][1] + b1);
                float2 v1 = make_float2(acc[mt][nt][2] + b0, acc[mt][nt][3] + b1);
                *(float2*)(out + (size_t)mg * CC + ng) = v0;
                *(float2*)(out + (size_t)(mg + 8) * CC + ng) = v1;
            }
        }
    } else {
        // q scale folds 1/sqrt(64) AND log2(e): attention softmax uses ex2.
#pragma unroll
        for (int mt = 0; mt < 4; mt++) {
#pragma unroll
            for (int nt = 0; nt < 4; nt++) {
                int mg = m0 + wm + mt * 16 + g;
                int ng = n0 + wn + nt * 8 + 2 * c4;
                int region = ng / CC;             // 0=q 1=k 2=v
                int cp = ng - region * CC;
                int h = cp >> 6, d = cp & 63;     // d even
                int bi = mg >> 10, t = mg & 1023;
                float b0 = bias[ng], b1 = bias[ng + 1];
                if (region == 2) {
                    // g_v layout [B,H,D,T]
                    float* dst = g_v + ((size_t)(bi * HH + h) * DD + d) * TT + t;
                    dst[0]      = tf32_round(acc[mt][nt][0] + b0);
                    dst[TT]     = tf32_round(acc[mt][nt][1] + b1);
                    dst[8]      = tf32_round(acc[mt][nt][2] + b0);
                    dst[TT + 8] = tf32_round(acc[mt][nt][3] + b1);
                } else {
                    float sc = (region == 0) ? 0.18033688011112042f : 1.0f;
                    float* base = (region == 0) ? g_q : g_k;
                    float* dst =
                        base + ((size_t)(bi * HH + h) * TT + t) * DD + d;
                    float2 v0 = make_float2(tf32_round((acc[mt][nt][0] + b0) * sc),
                                            tf32_round((acc[mt][nt][1] + b1) * sc));
                    float2 v1 = make_float2(tf32_round((acc[mt][nt][2] + b0) * sc),
                                            tf32_round((acc[mt][nt][3] + b1) * sc));
                    *(float2*)dst = v0;
                    *(float2*)(dst + 8 * DD) = v1;
                }
            }
        }
    }
}

// ---------------------------------------------------------------------------
// Causal flash attention on tf32 mma.sync + ldmatrix fragment loads.
// (proven R13 kernel, unchanged)
// ---------------------------------------------------------------------------
#define AKV 64
#define QSTR 68
#define KSTR 68
#define VSTR 68
#define PSTR 68
#define PS_OFF (128 * QSTR)                 // 8704
#define KV_OFF (PS_OFF + 128 * PSTR)        // 17408
#define KBUF_F (AKV * KSTR)                 // 4352
#define KVBUF_F (KBUF_F + AKV * VSTR)       // 8704
#define ATT_SMEMF (KV_OFF + 2 * KVBUF_F)    // 34816
#define ATT_SMEMB (ATT_SMEMF * 4)           // 139264

__global__ __launch_bounds__(256, 1) void attn_mma_kernel()
{
    extern __shared__ __align__(16) float sm[];
    const int tid = threadIdx.x;
    const int wid = tid >> 5;
    const int lane = tid & 31;
    const int g = lane >> 2;      // 0..7
    const int c4 = lane & 3;      // 0..3
    const int qt = 7 - (int)blockIdx.x;   // heavy tiles launch first
    const int bh = blockIdx.y;
    const int q0 = qt * 128;

    const float* Qg = g_q + (size_t)bh * (TT * DD) + (size_t)q0 * DD;
    const float* Kg = g_k + (size_t)bh * (TT * DD);
    const float* Vg = g_v + (size_t)bh * (DD * TT);   // [D][T]
    const uint32_t sb = smem_u32(sm);

    const int arow_l = ((lane >> 3) & 1) * 8 + (lane & 7);  // 0..15
    const int acol_l = (lane >> 4) * 4;                     // 0 or 4

    // Prologue: Q tile (128x64) + KV tile 0, one cp.async group.
#pragma unroll
    for (int i = 0; i < 8; i++) {
        int idx = tid + 256 * i;
        int r = idx >> 4, c = (idx & 15) * 4;
        cp_async16(sb + (r * QSTR + c) * 4, Qg + r * DD + c);
    }
#pragma unroll
    for (int i = 0; i < 4; i++) {
        int idx = tid + 256 * i;
        int r = idx >> 4, c = (idx & 15) * 4;
        cp_async16(sb + (KV_OFF + r * KSTR + c) * 4, Kg + r * DD + c);
        cp_async16(sb + (KV_OFF + KBUF_F + r * VSTR + c) * 4,
                   Vg + (size_t)r * TT + c);
    }
    CP_COMMIT();

    float o[8][4];
#pragma unroll
    for (int nt = 0; nt < 8; nt++)
#pragma unroll
        for (int i = 0; i < 4; i++) o[nt][i] = 0.0f;
    float m0 = -1e30f, m1 = -1e30f, l0 = 0.0f, l1 = 0.0f;

    const int ntiles = 2 * qt + 2;
    const uint32_t qaddr = sb + ((wid * 16 + arow_l) * QSTR + acol_l) * 4;
    const uint32_t paddr =
        sb + (PS_OFF + (wid * 16 + arow_l) * PSTR + acol_l) * 4;

    for (int j = 0; j < ntiles; j++) {
        const int buf = j & 1;
        if (j + 1 < ntiles) {
            const float* Kg2 = Kg + (size_t)(j + 1) * AKV * DD;
            const float* Vg2 = Vg + (j + 1) * AKV;   // column offset in [D][T]
            const uint32_t kvb = sb + (KV_OFF + (buf ^ 1) * KVBUF_F) * 4;
#pragma unroll
            for (int i = 0; i < 4; i++) {
                int idx = tid + 256 * i;
                int r = idx >> 4, c = (idx & 15) * 4;
                cp_async16(kvb + (r * KSTR + c) * 4, Kg2 + r * DD + c);
                cp_async16(kvb + (KBUF_F + r * VSTR + c) * 4,
                           Vg2 + (size_t)r * TT + c);
            }
            CP_COMMIT();
            CP_WAIT(1);
        } else {
            CP_WAIT(0);
        }
        __syncthreads();

        const uint32_t kbase = sb + (KV_OFF + buf * KVBUF_F) * 4 +
                               (arow_l * KSTR + acol_l) * 4;
        const uint32_t vbase = kbase + KBUF_F * 4;

        // S = Q @ K^T  (log2 domain; Q pre-scaled)
        float s[8][4];
#pragma unroll
        for (int nt = 0; nt < 8; nt++)
#pragma unroll
            for (int i = 0; i < 4; i++) s[nt][i] = 0.0f;

#pragma unroll
        for (int kk = 0; kk < 64; kk += 8) {
            uint32_t a[4];
            LDM_X4(a[0], a[1], a[2], a[3], qaddr + kk * 4);
#pragma unroll
            for (int i = 0; i < 4; i++) {
                uint32_t r0, r1, r2, r3;
                LDM_X4(r0, r1, r2, r3, kbase + (i * 16 * KSTR + kk) * 4);
                uint32_t b0[2] = {r0, r2}, b1[2] = {r1, r3};
                mma_tf32(s[2 * i], a, b0);
                mma_tf32(s[2 * i + 1], a, b1);
            }
        }

        // Causal mask (only the two diagonal-straddling tiles need it)
        if (j >= 2 * qt) {
            const int off = q0 - j * AKV;   // 0 or -64
            const int r0 = wid * 16 + g, r1 = r0 + 8;
#pragma unroll
            for (int nt = 0; nt < 8; nt++) {
                int col = nt * 8 + 2 * c4;
                if (col     > r0 + off) s[nt][0] = -1e30f;
                if (col + 1 > r0 + off) s[nt][1] = -1e30f;
                if (col     > r1 + off) s[nt][2] = -1e30f;
                if (col + 1 > r1 + off) s[nt][3] = -1e30f;
            }
        }

        // Online softmax (rows g and g+8; quad-wide reduction)
        float mx0 = -1e30f, mx1 = -1e30f;
#pragma unroll
        for (int nt = 0; nt < 8; nt++) {
            mx0 = fmaxf(mx0, fmaxf(s[nt][0], s[nt][1]));
            mx1 = fmaxf(mx1, fmaxf(s[nt][2], s[nt][3]));
        }
        mx0 = fmaxf(mx0, __shfl_xor_sync(0xffffffffu, mx0, 1));
        mx0 = fmaxf(mx0, __shfl_xor_sync(0xffffffffu, mx0, 2));
        mx1 = fmaxf(mx1, __shfl_xor_sync(0xffffffffu, mx1, 1));
        mx1 = fmaxf(mx1, __shfl_xor_sync(0xffffffffu, mx1, 2));

        float mn0 = fmaxf(m0, mx0), mn1 = fmaxf(m1, mx1);
        float corr0 = ex2(m0 - mn0), corr1 = ex2(m1 - mn1);
        m0 = mn0; m1 = mn1;

        float sum0 = 0.0f, sum1 = 0.0f;
#pragma unroll
        for (int nt = 0; nt < 8; nt++) {
            s[nt][0] = ex2(s[nt][0] - m0);
            s[nt][1] = ex2(s[nt][1] - m0);
            s[nt][2] = ex2(s[nt][2] - m1);
            s[nt][3] = ex2(s[nt][3] - m1);
            sum0 += s[nt][0] + s[nt][1];
            sum1 += s[nt][2] + s[nt][3];
        }
        sum0 += __shfl_xor_sync(0xffffffffu, sum0, 1);
        sum0 += __shfl_xor_sync(0xffffffffu, sum0, 2);
        sum1 += __shfl_xor_sync(0xffffffffu, sum1, 1);
        sum1 += __shfl_xor_sync(0xffffffffu, sum1, 2);
        l0 = l0 * corr0 + sum0;
        l1 = l1 * corr1 + sum1;

#pragma unroll
        for (int nt = 0; nt < 8; nt++) {
            o[nt][0] *= corr0; o[nt][1] *= corr0;
            o[nt][2] *= corr1; o[nt][3] *= corr1;
        }

        // Stage P (tf32-rounded) into warp-private smem rows
        __syncwarp();
        float* Pp = sm + PS_OFF + (wid * 16 + g) * PSTR;
#pragma unroll
        for (int nt = 0; nt < 8; nt++) {
            int col = nt * 8 + 2 * c4;
            *(float2*)(Pp + col) =
                make_float2(tf32_round(s[nt][0]), tf32_round(s[nt][1]));
            *(float2*)(Pp + 8 * PSTR + col) =
                make_float2(tf32_round(s[nt][2]), tf32_round(s[nt][3]));
        }
        __syncwarp();

        // O += P @ V   (V tile is [d][t]; B-frags ldmatrix'd like K)
#pragma unroll
        for (int kk = 0; kk < 64; kk += 8) {
            uint32_t a[4];
            LDM_X4(a[0], a[1], a[2], a[3], paddr + kk * 4);
#pragma unroll
            for (int i = 0; i < 4; i++) {
                uint32_t r0, r1, r2, r3;
                LDM_X4(r0, r1, r2, r3, vbase + (i * 16 * VSTR + kk) * 4);
                uint32_t b0[2] = {r0, r2}, b1[2] = {r1, r3};
                mma_tf32(o[2 * i], a, b0);
                mma_tf32(o[2 * i + 1], a, b1);
            }
        }
        __syncthreads();  // all warps done with this KV buffer
    }

    // Epilogue: normalize, tf32-round (proj input), store to g_y [B,T,C]
    const float il0 = 1.0f / l0, il1 = 1.0f / l1;
    const int bi = bh / HH, h = bh % HH;
    const int r0 = q0 + wid * 16 + g;
    float* dst0 = g_y + ((size_t)(bi * TT + r0)) * CC + h * DD;
    float* dst1 = dst0 + 8 * CC;
#pragma unroll
    for (int nt = 0; nt < 8; nt++) {
        int col = nt * 8 + 2 * c4;
        *(float2*)(dst0 + col) = make_float2(tf32_round(o[nt][0] * il0),
                                             tf32_round(o[nt][1] * il0));
        *(float2*)(dst1 + col) = make_float2(tf32_round(o[nt][2] * il1),
                                             tf32_round(o[nt][3] * il1));
    }
}

// ---------------------------------------------------------------------------
extern "C" void kernel_launch(void* const* d_in, const int* in_sizes, int n_in,
                              void* d_out, int out_size)
{
    const float* x      = (const float*)d_in[0];
    const float* w_qkv  = (const float*)d_in[1];
    const float* b_qkv  = (const float*)d_in[2];
    const float* w_proj = (const float*)d_in[3];
    const float* b_proj = (const float*)d_in[4];
    float* out = (float*)d_out;

    cudaFuncSetAttribute(mm_mma_kernel,
                         cudaFuncAttributeMaxDynamicSharedMemorySize, SMEMB);
    cudaFuncSetAttribute(attn_mma_kernel,
                         cudaFuncAttributeMaxDynamicSharedMemorySize, ATT_SMEMB);

    // tf32 rounding (x) + transpose-and-round (weights; output selected
    // inside device code — never pass device-global addresses from host)
    cvt_x_kernel<<<(N4_X + 255) / 256, 256>>>(x);
    cvt_wT_kernel<<<dim3(NQKV / 32, CC / 32), 256>>>(w_qkv, CC, NQKV, 0);
    cvt_wT_kernel<<<dim3(CC / 32, CC / 32), 256>>>(w_proj, CC, CC, 1);

    // QKV: [8192 x 768] @ [768 x 2304]
    mm_mma_kernel<<<dim3(NQKV / 128, NTOK / 128), 256, SMEMB>>>(
        b_qkv, nullptr, NQKV, 0);
    // Attention: tf32 mma flash, 128-row Q tiles, ldmatrix frags
    attn_mma_kernel<<<dim3(TT / 128, BB * HH), 256, ATT_SMEMB>>>();
    // Proj: [8192 x 768] @ [768 x 768]
    mm_mma_kernel<<<dim3(CC / 128, NTOK / 128), 256, SMEMB>>>(
        b_proj, out, CC, 1);
}

// round 17
// speedup vs baseline: 2.1462x; 2.1462x over previous
#include <cuda_runtime.h>
#include <cuda_fp16.h>
#include <cstdint>

// Problem constants
#define BB 8
#define TT 1024
#define CC 768
#define HH 12
#define DD 64
#define NTOK (BB * TT)      // 8192
#define NQKV (3 * CC)       // 2304

// Scratch (device globals; no runtime allocation allowed).  All fp16 arrays
// are 16B-aligned for cp.async.
__device__ __align__(16) __half g_qh[BB * HH * TT * DD]; // [B,H,T,D], q*log2e/8
__device__ __align__(16) __half g_kh[BB * HH * TT * DD]; // [B,H,T,D]
__device__ __align__(16) __half g_vh[BB * HH * TT * DD]; // [B,H,T,D]
__device__ __align__(16) __half g_yh[BB * TT * CC];      // attention out [B,T,C]
__device__ __align__(16) __half g_xh[NTOK * CC];         // x, fp16
__device__ __align__(16) __half g_wqh[CC * NQKV];        // w_qkv [k][n], fp16
__device__ __align__(16) __half g_wph[CC * CC];          // w_proj [k][n], fp16

// ---------------------------------------------------------------------------
// Helpers (compute_80-level PTX only)
// ---------------------------------------------------------------------------
__device__ __forceinline__ uint32_t smem_u32(const void* p) {
    uint32_t a;
    asm("{ .reg .u64 t; cvta.to.shared.u64 t, %1; cvt.u32.u64 %0, t; }"
        : "=r"(a) : "l"(p));
    return a;
}
__device__ __forceinline__ float ex2(float x) {
    float y;
    asm("ex2.approx.ftz.f32 %0, %1;" : "=f"(y) : "f"(x));
    return y;
}
__device__ __forceinline__ uint32_t packh2(float lo, float hi) {
    __half2 h = __floats2half2_rn(lo, hi);
    return *(uint32_t*)&h;
}
__device__ __forceinline__ void cp_async16(uint32_t dst, const void* src) {
    asm volatile("cp.async.ca.shared.global [%0], [%1], 16;"
                 :: "r"(dst), "l"(src));
}
#define CP_COMMIT() asm volatile("cp.async.commit_group;" ::: "memory")
#define CP_WAIT(n)  asm volatile("cp.async.wait_group %0;" :: "n"(n) : "memory")

// m16n8k16 fp16 mma, fp32 accumulate.
__device__ __forceinline__ void mma_f16(float* d, const uint32_t* a,
                                        uint32_t b0, uint32_t b1) {
    asm volatile(
        "mma.sync.aligned.m16n8k16.row.col.f32.f16.f16.f32 "
        "{%0,%1,%2,%3}, {%4,%5,%6,%7}, {%8,%9}, {%0,%1,%2,%3};"
        : "+f"(d[0]), "+f"(d[1]), "+f"(d[2]), "+f"(d[3])
        : "r"(a[0]), "r"(a[1]), "r"(a[2]), "r"(a[3]), "r"(b0), "r"(b1));
}

#define LDM_X4(r0, r1, r2, r3, addr) \
    asm volatile("ldmatrix.sync.aligned.m8n8.x4.shared.b16 {%0,%1,%2,%3}, [%4];" \
                 : "=r"(r0), "=r"(r1), "=r"(r2), "=r"(r3) : "r"(addr))
#define LDM_X4T(r0, r1, r2, r3, addr) \
    asm volatile("ldmatrix.sync.aligned.m8n8.x4.trans.shared.b16 {%0,%1,%2,%3}, [%4];" \
                 : "=r"(r0), "=r"(r1), "=r"(r2), "=r"(r3) : "r"(addr))

// ---------------------------------------------------------------------------
// Single fused fp32 -> fp16 conversion pass over x, w_qkv, w_proj.
// All region sizes are multiples of 1024 floats.
// ---------------------------------------------------------------------------
#define N4_X  (NTOK * CC / 4)     // 1572864
#define N4_WQ (CC * NQKV / 4)     // 442368
#define N4_WP (CC * CC / 4)       // 147456
#define CVT_BLOCKS ((N4_X + N4_WQ + N4_WP) / 256)   // 8448

__global__ __launch_bounds__(256) void cvt_all_kernel(
    const float* __restrict__ x, const float* __restrict__ wq,
    const float* __restrict__ wp)
{
    int i = blockIdx.x * 256 + threadIdx.x;
    const float* src;
    __half* dst;
    if (i < N4_X) {
        src = x; dst = g_xh;
    } else if (i < N4_X + N4_WQ) {
        i -= N4_X; src = wq; dst = g_wqh;
    } else {
        i -= N4_X + N4_WQ; src = wp; dst = g_wph;
    }
    float4 v = ((const float4*)src)[i];
    ((__half2*)dst)[2 * i]     = __floats2half2_rn(v.x, v.y);
    ((__half2*)dst)[2 * i + 1] = __floats2half2_rn(v.z, v.w);
}

// ---------------------------------------------------------------------------
// fp16 mma.sync GEMM: out[M,Ntot] = A[M,768] @ W + bias, W [768][Ntot].
// CTA 128x128, 256 thr (8 warps as 2m x 4n), warp tile 64x32.
// KTILE 64 (4 k16-steps), 2-stage cp.async.
// As: m-major [128][72] fp16 (ldmatrix rows: stride 36 words -> 4r banks, OK)
// Bs: k-major [64][136] fp16 (trans ldmatrix rows: stride 68 words -> 4r, OK)
// mode 0: QKV epilogue (fp16 scatter to g_qh/g_kh/g_vh; q * log2e/8)
// mode 1: fp32 row-major store to out
// ---------------------------------------------------------------------------
#define KTILE 64
#define NIT (CC / KTILE)        // 12
#define ASTR 72
#define BSTR 136
#define ABY (128 * ASTR * 2)    // 18432
#define BBY (KTILE * BSTR * 2)  // 17408
#define BUFB (ABY + BBY)        // 35840
#define SMEMB (2 * BUFB)        // 71680

__device__ __forceinline__ void mm_issue_tile(
    const __half* __restrict__ A, const __half* __restrict__ W,
    uint32_t sbuf, int m0, int n0, int k0, int Ntot, int tid)
{
#pragma unroll
    for (int i = 0; i < 4; i++) {
        int idx = tid + 256 * i;
        int m = idx >> 3, kq = idx & 7;               // 8 x 16B chunks per row
        cp_async16(sbuf + (m * ASTR + kq * 8) * 2,
                   A + (size_t)(m0 + m) * CC + k0 + kq * 8);
    }
#pragma unroll
    for (int i = 0; i < 4; i++) {
        int idx = tid + 256 * i;
        int k = idx >> 4, nq = idx & 15;              // 16 x 16B chunks per row
        cp_async16(sbuf + ABY + (k * BSTR + nq * 8) * 2,
                   W + (size_t)(k0 + k) * Ntot + n0 + nq * 8);
    }
    CP_COMMIT();
}

__global__ void __launch_bounds__(256, 2) mm_mma_kernel(
    const float* __restrict__ bias, float* __restrict__ out,
    int Ntot, int mode)
{
    extern __shared__ __align__(16) char smem[];
    const __half* A = (mode == 0) ? g_xh : g_yh;
    const __half* W = (mode == 0) ? g_wqh : g_wph;

    const int tid = threadIdx.x;
    const int wid = tid >> 5;
    const int lane = tid & 31;
    const int g = lane >> 2;
    const int c4 = lane & 3;
    const int m0 = blockIdx.y * 128;
    const int n0 = blockIdx.x * 128;
    const int wm = (wid >> 2) * 64;
    const int wn = (wid & 3) * 32;
    const uint32_t sbase = smem_u32(smem);

    // ldmatrix lane geometry
    const int arow = lane & 15;                 // A matrices: rows 0..15
    const int acol8 = (lane >> 4) * 8;          // +8 halfs for k-hi matrices
    const int bk = ((lane >> 3) & 1) * 8 + (lane & 7);  // B(trans): k row
    const int bn8 = (lane >> 4) * 8;                    // B: n offset

    float acc[4][4][4];
#pragma unroll
    for (int mt = 0; mt < 4; mt++)
#pragma unroll
        for (int nt = 0; nt < 4; nt++)
#pragma unroll
            for (int i = 0; i < 4; i++) acc[mt][nt][i] = 0.0f;

    mm_issue_tile(A, W, sbase, m0, n0, 0, Ntot, tid);

    for (int t = 0; t < NIT; t++) {
        const int buf = t & 1;
        if (t + 1 < NIT) {
            mm_issue_tile(A, W, sbase + (buf ^ 1) * BUFB,
                          m0, n0, (t + 1) * KTILE, Ntot, tid);
            CP_WAIT(1);
        } else {
            CP_WAIT(0);
        }
        __syncthreads();

        const uint32_t sbuf = sbase + buf * BUFB;
        const uint32_t aaddr = sbuf + ((wm + arow) * ASTR + acol8) * 2;
        const uint32_t baddr = sbuf + ABY + (bk * BSTR + wn + bn8) * 2;

#pragma unroll
        for (int kk = 0; kk < KTILE; kk += 16) {
            uint32_t a[4][4], b[4][2];
#pragma unroll
            for (int mt = 0; mt < 4; mt++)
                LDM_X4(a[mt][0], a[mt][1], a[mt][2], a[mt][3],
                       aaddr + (mt * 16 * ASTR + kk) * 2);
            LDM_X4T(b[0][0], b[0][1], b[1][0], b[1][1],
                    baddr + (kk * BSTR) * 2);
            LDM_X4T(b[2][0], b[2][1], b[3][0], b[3][1],
                    baddr + (kk * BSTR + 16) * 2);
#pragma unroll
            for (int mt = 0; mt < 4; mt++)
#pragma unroll
                for (int nt = 0; nt < 4; nt++)
                    mma_f16(acc[mt][nt], a[mt], b[nt][0], b[nt][1]);
        }
        __syncthreads();
    }

    // Epilogue.  Fragment (mt,nt): rows g,g+8; cols 2c4,2c4+1.
    if (mode == 1) {
#pragma unroll
        for (int mt = 0; mt < 4; mt++) {
#pragma unroll
            for (int nt = 0; nt < 4; nt++) {
                int mg = m0 + wm + mt * 16 + g;
                int ng = n0 + wn + nt * 8 + 2 * c4;
                float b0 = bias[ng], b1 = bias[ng + 1];
                float2 v0 = make_float2(acc[mt][nt][0] + b0, acc[mt][nt][1] + b1);
                float2 v1 = make_float2(acc[mt][nt][2] + b0, acc[mt][nt][3] + b1);
                *(float2*)(out + (size_t)mg * CC + ng) = v0;
                *(float2*)(out + (size_t)(mg + 8) * CC + ng) = v1;
            }
        }
    } else {
        // q scale folds 1/sqrt(64) AND log2(e): attention softmax uses ex2.
#pragma unroll
        for (int mt = 0; mt < 4; mt++) {
#pragma unroll
            for (int nt = 0; nt < 4; nt++) {
                int mg = m0 + wm + mt * 16 + g;
                int ng = n0 + wn + nt * 8 + 2 * c4;
                int region = ng / CC;             // 0=q 1=k 2=v
                int cp = ng - region * CC;
                int h = cp >> 6, d = cp & 63;     // d even
                int bi = mg >> 10, t = mg & 1023;
                float sc = (region == 0) ? 0.18033688011112042f : 1.0f;
                __half* base = (region == 0) ? g_qh : (region == 1) ? g_kh : g_vh;
                __half* dst = base + ((size_t)(bi * HH + h) * TT + t) * DD + d;
                float b0 = bias[ng], b1 = bias[ng + 1];
                *(__half2*)dst =
                    __floats2half2_rn((acc[mt][nt][0] + b0) * sc,
                                      (acc[mt][nt][1] + b1) * sc);
                *(__half2*)(dst + 8 * DD) =
                    __floats2half2_rn((acc[mt][nt][2] + b0) * sc,
                                      (acc[mt][nt][3] + b1) * sc);
            }
        }
    }
}

// ---------------------------------------------------------------------------
// Causal flash attention, fp16 m16n8k16 + ldmatrix; P kept in registers
// (C-fragment layout == A-fragment layout for m16n8k16).
// CTA = 128 Q rows x one (b,h); 8 warps, warp w owns rows w*16..w*16+15.
// KV tiles of 64, cp.async double-buffered.  All smem strides 72 fp16
// (36 words -> ldmatrix row banks 4r: conflict-free).
// ---------------------------------------------------------------------------
#define AKV 64
#define QSTRH 72
#define Q_BY (128 * QSTRH * 2)          // 18432
#define K_BY (AKV * QSTRH * 2)          // 9216
#define KVBUF_BY (2 * K_BY)             // 18432
#define ATT_SMEMB (Q_BY + 2 * KVBUF_BY) // 55296

__global__ __launch_bounds__(256, 2) void attn_mma_kernel()
{
    extern __shared__ __align__(16) char smc[];
    const int tid = threadIdx.x;
    const int wid = tid >> 5;
    const int lane = tid & 31;
    const int g = lane >> 2;      // 0..7
    const int c4 = lane & 3;      // 0..3
    const int qt = 7 - (int)blockIdx.x;   // heavy tiles launch first
    const int bh = blockIdx.y;
    const int q0 = qt * 128;

    const __half* Qg = g_qh + (size_t)bh * (TT * DD) + (size_t)q0 * DD;
    const __half* Kg = g_kh + (size_t)bh * (TT * DD);
    const __half* Vg = g_vh + (size_t)bh * (TT * DD);
    const uint32_t sb = smem_u32(smc);

    // ldmatrix lane geometry
    const int arow = lane & 15;               // A: rows 0..15
    const int acol8 = (lane >> 4) * 8;        // A: +8 halfs (k-hi)
    const int kkv = (lane >> 4) * 8 + (lane & 7);        // K(non-trans): kv row
    const int kd8 = ((lane >> 3) & 1) * 8;               // K: d offset
    const int vkv = ((lane >> 3) & 1) * 8 + (lane & 7);  // V(trans): kv row
    const int vd8 = (lane >> 4) * 8;                     // V: d offset

    // Prologue: Q tile (128x64) + KV tile 0, one cp.async group.
#pragma unroll
    for (int i = 0; i < 4; i++) {
        int idx = tid + 256 * i;
        int r = idx >> 3, c8 = (idx & 7) * 8;
        cp_async16(sb + (r * QSTRH + c8) * 2, Qg + r * DD + c8);
    }
#pragma unroll
    for (int i = 0; i < 2; i++) {
        int idx = tid + 256 * i;
        int r = idx >> 3, c8 = (idx & 7) * 8;
        cp_async16(sb + Q_BY + (r * QSTRH + c8) * 2, Kg + r * DD + c8);
        cp_async16(sb + Q_BY + K_BY + (r * QSTRH + c8) * 2, Vg + r * DD + c8);
    }
    CP_COMMIT();

    float o[8][4];
#pragma unroll
    for (int nt = 0; nt < 8; nt++)
#pragma unroll
        for (int i = 0; i < 4; i++) o[nt][i] = 0.0f;
    float m0 = -1e30f, m1 = -1e30f, l0 = 0.0f, l1 = 0.0f;

    const int ntiles = 2 * qt + 2;
    const uint32_t qaddr = sb + ((wid * 16 + arow) * QSTRH + acol8) * 2;

    for (int j = 0; j < ntiles; j++) {
        const int buf = j & 1;
        if (j + 1 < ntiles) {
            const __half* Kg2 = Kg + (size_t)(j + 1) * AKV * DD;
            const __half* Vg2 = Vg + (size_t)(j + 1) * AKV * DD;
            const uint32_t kvb = sb + Q_BY + (buf ^ 1) * KVBUF_BY;
#pragma unroll
            for (int i = 0; i < 2; i++) {
                int idx = tid + 256 * i;
                int r = idx >> 3, c8 = (idx & 7) * 8;
                cp_async16(kvb + (r * QSTRH + c8) * 2, Kg2 + r * DD + c8);
                cp_async16(kvb + K_BY + (r * QSTRH + c8) * 2, Vg2 + r * DD + c8);
            }
            CP_COMMIT();
            CP_WAIT(1);
        } else {
            CP_WAIT(0);
        }
        __syncthreads();

        const uint32_t kbase = sb + Q_BY + buf * KVBUF_BY +
                               (kkv * QSTRH + kd8) * 2;
        const uint32_t vbase = sb + Q_BY + buf * KVBUF_BY + K_BY +
                               (vkv * QSTRH + vd8) * 2;

        // S = Q @ K^T  (log2 domain; Q pre-scaled)
        float s[8][4];
#pragma unroll
        for (int nt = 0; nt < 8; nt++)
#pragma unroll
            for (int i = 0; i < 4; i++) s[nt][i] = 0.0f;

#pragma unroll
        for (int kk8 = 0; kk8 < 4; kk8++) {
            const int kk = kk8 * 16;
            uint32_t a[4];
            LDM_X4(a[0], a[1], a[2], a[3], qaddr + kk * 2);
#pragma unroll
            for (int i = 0; i < 4; i++) {
                uint32_t r0, r1, r2, r3;
                LDM_X4(r0, r1, r2, r3, kbase + (i * 16 * QSTRH + kk) * 2);
                mma_f16(s[2 * i], a, r0, r1);
                mma_f16(s[2 * i + 1], a, r2, r3);
            }
        }

        // Causal mask (only the two diagonal-straddling tiles need it)
        if (j >= 2 * qt) {
            const int off = q0 - j * AKV;   // 0 or -64
            const int r0 = wid * 16 + g, r1 = r0 + 8;
#pragma unroll
            for (int nt = 0; nt < 8; nt++) {
                int col = nt * 8 + 2 * c4;
                if (col     > r0 + off) s[nt][0] = -1e30f;
                if (col + 1 > r0 + off) s[nt][1] = -1e30f;
                if (col     > r1 + off) s[nt][2] = -1e30f;
                if (col + 1 > r1 + off) s[nt][3] = -1e30f;
            }
        }

        // Online softmax (rows g and g+8; quad-wide reduction)
        float mx0 = -1e30f, mx1 = -1e30f;
#pragma unroll
        for (int nt = 0; nt < 8; nt++) {
            mx0 = fmaxf(mx0, fmaxf(s[nt][0], s[nt][1]));
            mx1 = fmaxf(mx1, fmaxf(s[nt][2], s[nt][3]));
        }
        mx0 = fmaxf(mx0, __shfl_xor_sync(0xffffffffu, mx0, 1));
        mx0 = fmaxf(mx0, __shfl_xor_sync(0xffffffffu, mx0, 2));
        mx1 = fmaxf(mx1, __shfl_xor_sync(0xffffffffu, mx1, 1));
        mx1 = fmaxf(mx1, __shfl_xor_sync(0xffffffffu, mx1, 2));

        float mn0 = fmaxf(m0, mx0), mn1 = fmaxf(m1, mx1);
        float corr0 = ex2(m0 - mn0), corr1 = ex2(m1 - mn1);
        m0 = mn0; m1 = mn1;

        float sum0 = 0.0f, sum1 = 0.0f;
#pragma unroll
        for (int nt = 0; nt < 8; nt++) {
            s[nt][0] = ex2(s[nt][0] - m0);
            s[nt][1] = ex2(s[nt][1] - m0);
            s[nt][2] = ex2(s[nt][2] - m1);
            s[nt][3] = ex2(s[nt][3] - m1);
            sum0 += s[nt][0] + s[nt][1];
            sum1 += s[nt][2] + s[nt][3];
        }
        sum0 += __shfl_xor_sync(0xffffffffu, sum0, 1);
        sum0 += __shfl_xor_sync(0xffffffffu, sum0, 2);
        sum1 += __shfl_xor_sync(0xffffffffu, sum1, 1);
        sum1 += __shfl_xor_sync(0xffffffffu, sum1, 2);
        l0 = l0 * corr0 + sum0;
        l1 = l1 * corr1 + sum1;

#pragma unroll
        for (int nt = 0; nt < 8; nt++) {
            o[nt][0] *= corr0; o[nt][1] *= corr0;
            o[nt][2] *= corr1; o[nt][3] *= corr1;
        }

        // O += P @ V.  P converted in-register to fp16 A-fragments.
#pragma unroll
        for (int i = 0; i < 4; i++) {     // kv k16 chunks
            uint32_t a[4];
            a[0] = packh2(s[2 * i][0], s[2 * i][1]);
            a[1] = packh2(s[2 * i][2], s[2 * i][3]);
            a[2] = packh2(s[2 * i + 1][0], s[2 * i + 1][1]);
            a[3] = packh2(s[2 * i + 1][2], s[2 * i + 1][3]);
#pragma unroll
            for (int jd = 0; jd < 4; jd++) {   // d16 chunks
                uint32_t r0, r1, r2, r3;
                LDM_X4T(r0, r1, r2, r3,
                        vbase + (i * 16 * QSTRH + jd * 16) * 2);
                mma_f16(o[2 * jd], a, r0, r1);
                mma_f16(o[2 * jd + 1], a, r2, r3);
            }
        }
        __syncthreads();  // all warps done with this KV buffer
    }

    // Epilogue: normalize, store fp16 to g_yh [B,T,C] (proj input)
    const float il0 = 1.0f / l0, il1 = 1.0f / l1;
    const int bi = bh / HH, h = bh % HH;
    const int r0 = q0 + wid * 16 + g;
    __half* dst0 = g_yh + ((size_t)(bi * TT + r0)) * CC + h * DD;
    __half* dst1 = dst0 + 8 * CC;
#pragma unroll
    for (int nt = 0; nt < 8; nt++) {
        int col = nt * 8 + 2 * c4;
        *(__half2*)(dst0 + col) = __floats2half2_rn(o[nt][0] * il0,
                                                    o[nt][1] * il0);
        *(__half2*)(dst1 + col) = __floats2half2_rn(o[nt][2] * il1,
                                                    o[nt][3] * il1);
    }
}

// ---------------------------------------------------------------------------
extern "C" void kernel_launch(void* const* d_in, const int* in_sizes, int n_in,
                              void* d_out, int out_size)
{
    const float* x      = (const float*)d_in[0];
    const float* w_qkv  = (const float*)d_in[1];
    const float* b_qkv  = (const float*)d_in[2];
    const float* w_proj = (const float*)d_in[3];
    const float* b_proj = (const float*)d_in[4];
    float* out = (float*)d_out;

    cudaFuncSetAttribute(mm_mma_kernel,
                         cudaFuncAttributeMaxDynamicSharedMemorySize, SMEMB);
    cudaFuncSetAttribute(attn_mma_kernel,
                         cudaFuncAttributeMaxDynamicSharedMemorySize, ATT_SMEMB);

    // fp16 conversion of all GEMM inputs, one launch
    cvt_all_kernel<<<CVT_BLOCKS, 256>>>(x, w_qkv, w_proj);

    // QKV: [8192 x 768] @ [768 x 2304]
    mm_mma_kernel<<<dim3(NQKV / 128, NTOK / 128), 256, SMEMB>>>(
        b_qkv, nullptr, NQKV, 0);
    // Attention: fp16 mma flash, 128-row Q tiles, register-resident P
    attn_mma_kernel<<<dim3(TT / 128, BB * HH), 256, ATT_SMEMB>>>();
    // Proj: [8192 x 768] @ [768 x 768]
    mm_mma_kernel<<<dim3(CC / 128, NTOK / 128), 256, SMEMB>>>(
        b_proj, out, CC, 1);
}